// round 8
// baseline (speedup 1.0000x reference)

#include <cuda_runtime.h>
#include <math.h>

// Problem constants
#define BSZ 4
#define SEQ 2048
#define CH  768
#define NH  12
#define HD  64
#define TOK (BSZ*SEQ)   // 8192
#define C3  (3*CH)      // 2304
#define BH  (BSZ*NH)    // 48

// Scratch (allocation-free per harness rules)
__device__ float g_xn[TOK*CH];
__device__ float g_q[BH*SEQ*HD];
__device__ float g_k[BH*SEQ*HD];
__device__ float g_v[BH*SEQ*HD];
__device__ float g_att[TOK*CH];

// ---------------------------------------------------------------------------
// 1) LayerNorm: one block per token, 256 threads, 3 elems/thread
// ---------------------------------------------------------------------------
__global__ void ln_kernel(const float* __restrict__ x,
                          const float* __restrict__ gamma,
                          const float* __restrict__ beta) {
    int t = blockIdx.x;
    const float* xr = x + (size_t)t * CH;
    int i0 = threadIdx.x, i1 = i0 + 256, i2 = i0 + 512;
    float v0 = xr[i0], v1 = xr[i1], v2 = xr[i2];
    float s  = v0 + v1 + v2;
    float s2 = v0*v0 + v1*v1 + v2*v2;
    #pragma unroll
    for (int o = 16; o > 0; o >>= 1) {
        s  += __shfl_down_sync(0xffffffffu, s,  o);
        s2 += __shfl_down_sync(0xffffffffu, s2, o);
    }
    __shared__ float ws[8], ws2[8];
    __shared__ float mu_s, inv_s;
    int w = threadIdx.x >> 5, l = threadIdx.x & 31;
    if (l == 0) { ws[w] = s; ws2[w] = s2; }
    __syncthreads();
    if (threadIdx.x == 0) {
        float a = 0.f, b = 0.f;
        #pragma unroll
        for (int k = 0; k < 8; k++) { a += ws[k]; b += ws2[k]; }
        float mu  = a * (1.0f / CH);
        float var = b * (1.0f / CH) - mu * mu;
        mu_s  = mu;
        inv_s = rsqrtf(var + 1e-5f);
    }
    __syncthreads();
    float mu = mu_s, inv = inv_s;
    float* orow = g_xn + (size_t)t * CH;
    orow[i0] = (v0 - mu) * inv * gamma[i0] + beta[i0];
    orow[i1] = (v1 - mu) * inv * gamma[i1] + beta[i1];
    orow[i2] = (v2 - mu) * inv * gamma[i2] + beta[i2];
}

// ---------------------------------------------------------------------------
// 2) QKV GEMM: g_xn[8192,768] @ w_qkv[768,2304], epilogue scatters to
//    head-major Q/K/V [BH, SEQ, HD]. Tiles 64x64x16, 4x4 per thread.
// ---------------------------------------------------------------------------
__global__ void gemm_qkv_kernel(const float* __restrict__ W) {
    __shared__ float As[16][64];   // A^T: [k][m]
    __shared__ float Bs[16][64];   // [k][n]
    int tid = threadIdx.x;
    int tx = tid & 15, ty = tid >> 4;
    int m0 = blockIdx.y * 64;
    int n0 = blockIdx.x * 64;
    float acc[4][4] = {};
    int ar = tid >> 2;        // 0..63  (A tile row = m)
    int ac = (tid & 3) * 4;   // 0,4,8,12 (A tile col = k)
    int bk = tid >> 4;        // 0..15
    int bn = (tid & 15) * 4;  // 0..60

    for (int k0 = 0; k0 < CH; k0 += 16) {
        float4 av = *(const float4*)&g_xn[(size_t)(m0 + ar) * CH + k0 + ac];
        As[ac + 0][ar] = av.x; As[ac + 1][ar] = av.y;
        As[ac + 2][ar] = av.z; As[ac + 3][ar] = av.w;
        *(float4*)&Bs[bk][bn] = *(const float4*)&W[(size_t)(k0 + bk) * C3 + n0 + bn];
        __syncthreads();
        #pragma unroll
        for (int kc = 0; kc < 16; kc++) {
            float4 a = *(float4*)&As[kc][ty * 4];
            float4 b = *(float4*)&Bs[kc][tx * 4];
            float aa[4] = {a.x, a.y, a.z, a.w};
            float bb[4] = {b.x, b.y, b.z, b.w};
            #pragma unroll
            for (int i = 0; i < 4; i++)
                #pragma unroll
                for (int j = 0; j < 4; j++)
                    acc[i][j] += aa[i] * bb[j];
        }
        __syncthreads();
    }
    // Epilogue: which of q/k/v, which head (constant across the 64-wide tile)
    int which = n0 / CH;
    int h     = (n0 % CH) >> 6;
    int dbase = tx * 4;
    float* dst = (which == 0) ? g_q : ((which == 1) ? g_k : g_v);
    #pragma unroll
    for (int i = 0; i < 4; i++) {
        int m = m0 + ty * 4 + i;
        int b = m >> 11;        // / SEQ
        int n = m & (SEQ - 1);
        float4 v = make_float4(acc[i][0], acc[i][1], acc[i][2], acc[i][3]);
        *(float4*)&dst[((size_t)(b * NH + h) * SEQ + n) * HD + dbase] = v;
    }
}

// ---------------------------------------------------------------------------
// 3) Flash attention: one block = 64 query rows of one (b,h).
//    Online softmax, shfl row reductions, K-smem buffer reused for P.
// ---------------------------------------------------------------------------
__global__ void attn_kernel() {
    __shared__ float QsT[64][64];  // [d][q]
    __shared__ float KPs[64][64];  // phase 1: K^T [d][kv]; phase 2: P [q][kv]
    __shared__ float Vs[64][64];   // [kv][d]

    int tid = threadIdx.x;
    int tx = tid & 15, ty = tid >> 4;
    int bh = blockIdx.y;
    int q0 = blockIdx.x * 64;
    const float scale = 0.125f;  // 1/sqrt(64)

    const float* Qg = g_q + (size_t)bh * SEQ * HD;
    const float* Kg = g_k + (size_t)bh * SEQ * HD;
    const float* Vg = g_v + (size_t)bh * SEQ * HD;

    int lr = tid >> 2;        // 0..63
    int lc = (tid & 3) * 16;  // 0,16,32,48

    // Load Q tile transposed + pre-scaled
    #pragma unroll
    for (int u = 0; u < 4; u++) {
        float4 v = *(const float4*)&Qg[(size_t)(q0 + lr) * HD + lc + u * 4];
        QsT[lc + u*4 + 0][lr] = v.x * scale;
        QsT[lc + u*4 + 1][lr] = v.y * scale;
        QsT[lc + u*4 + 2][lr] = v.z * scale;
        QsT[lc + u*4 + 3][lr] = v.w * scale;
    }

    float m_i[4], l_i[4], o[4][4];
    #pragma unroll
    for (int i = 0; i < 4; i++) {
        m_i[i] = -1e30f; l_i[i] = 0.f;
        #pragma unroll
        for (int j = 0; j < 4; j++) o[i][j] = 0.f;
    }

    for (int s0 = 0; s0 < SEQ; s0 += 64) {
        __syncthreads();  // previous iteration done reading KPs/Vs
        #pragma unroll
        for (int u = 0; u < 4; u++) {
            float4 kv = *(const float4*)&Kg[(size_t)(s0 + lr) * HD + lc + u * 4];
            KPs[lc + u*4 + 0][lr] = kv.x;
            KPs[lc + u*4 + 1][lr] = kv.y;
            KPs[lc + u*4 + 2][lr] = kv.z;
            KPs[lc + u*4 + 3][lr] = kv.w;
            float4 vv = *(const float4*)&Vg[(size_t)(s0 + lr) * HD + lc + u * 4];
            *(float4*)&Vs[lr][lc + u * 4] = vv;
        }
        __syncthreads();

        // S = Q K^T (scaled): 4x4 per thread, rows ty*4+i, cols tx*4+j
        float s[4][4] = {};
        #pragma unroll
        for (int d = 0; d < 64; d++) {
            float4 a = *(float4*)&QsT[d][ty * 4];
            float4 b = *(float4*)&KPs[d][tx * 4];
            float aa[4] = {a.x, a.y, a.z, a.w};
            float bb[4] = {b.x, b.y, b.z, b.w};
            #pragma unroll
            for (int i = 0; i < 4; i++)
                #pragma unroll
                for (int j = 0; j < 4; j++)
                    s[i][j] += aa[i] * bb[j];
        }

        // Online softmax. Row spread over 16 lanes (tx); shfl_xor 1..8 stays
        // in the 16-lane group since lane = (ty&1)*16 + tx.
        #pragma unroll
        for (int i = 0; i < 4; i++) {
            float mx = fmaxf(fmaxf(s[i][0], s[i][1]), fmaxf(s[i][2], s[i][3]));
            #pragma unroll
            for (int off = 8; off > 0; off >>= 1)
                mx = fmaxf(mx, __shfl_xor_sync(0xffffffffu, mx, off));
            float mnew = fmaxf(m_i[i], mx);
            float f = __expf(m_i[i] - mnew);
            float rs = 0.f;
            #pragma unroll
            for (int j = 0; j < 4; j++) {
                s[i][j] = __expf(s[i][j] - mnew);
                rs += s[i][j];
            }
            #pragma unroll
            for (int off = 8; off > 0; off >>= 1)
                rs += __shfl_xor_sync(0xffffffffu, rs, off);
            l_i[i] = l_i[i] * f + rs;
            m_i[i] = mnew;
            #pragma unroll
            for (int j = 0; j < 4; j++) o[i][j] *= f;
        }

        __syncthreads();  // done reading KPs as K
        // Write P row-major: P[q][kv]
        #pragma unroll
        for (int i = 0; i < 4; i++)
            #pragma unroll
            for (int j = 0; j < 4; j++)
                KPs[ty * 4 + i][tx * 4 + j] = s[i][j];
        __syncthreads();

        // O += P @ V  (kv tiled by 4 for vector loads)
        #pragma unroll
        for (int kk0 = 0; kk0 < 16; kk0++) {
            float4 bv[4];
            #pragma unroll
            for (int u = 0; u < 4; u++)
                bv[u] = *(float4*)&Vs[kk0 * 4 + u][tx * 4];
            #pragma unroll
            for (int i = 0; i < 4; i++) {
                float4 a = *(float4*)&KPs[ty * 4 + i][kk0 * 4];
                float aa[4] = {a.x, a.y, a.z, a.w};
                #pragma unroll
                for (int u = 0; u < 4; u++) {
                    float bb[4] = {bv[u].x, bv[u].y, bv[u].z, bv[u].w};
                    #pragma unroll
                    for (int j = 0; j < 4; j++)
                        o[i][j] += aa[u] * bb[j];
                }
            }
        }
    }

    // Epilogue: normalize, write token-major [B,N,C]
    int b = bh / NH, h = bh % NH;
    #pragma unroll
    for (int i = 0; i < 4; i++) {
        int r = q0 + ty * 4 + i;
        float invl = 1.0f / l_i[i];
        float4 v = make_float4(o[i][0]*invl, o[i][1]*invl, o[i][2]*invl, o[i][3]*invl);
        *(float4*)&g_att[((size_t)(b * SEQ + r)) * CH + h * HD + tx * 4] = v;
    }
}

// ---------------------------------------------------------------------------
// 4) Output GEMM + bias + residual: g_att[8192,768] @ w_out[768,768]
// ---------------------------------------------------------------------------
__global__ void gemm_out_kernel(const float* __restrict__ W,
                                const float* __restrict__ bias,
                                const float* __restrict__ resid,
                                float* __restrict__ out) {
    __shared__ float As[16][64];
    __shared__ float Bs[16][64];
    int tid = threadIdx.x;
    int tx = tid & 15, ty = tid >> 4;
    int m0 = blockIdx.y * 64;
    int n0 = blockIdx.x * 64;
    float acc[4][4] = {};
    int ar = tid >> 2;
    int ac = (tid & 3) * 4;
    int bk = tid >> 4;
    int bn = (tid & 15) * 4;

    for (int k0 = 0; k0 < CH; k0 += 16) {
        float4 av = *(const float4*)&g_att[(size_t)(m0 + ar) * CH + k0 + ac];
        As[ac + 0][ar] = av.x; As[ac + 1][ar] = av.y;
        As[ac + 2][ar] = av.z; As[ac + 3][ar] = av.w;
        *(float4*)&Bs[bk][bn] = *(const float4*)&W[(size_t)(k0 + bk) * CH + n0 + bn];
        __syncthreads();
        #pragma unroll
        for (int kc = 0; kc < 16; kc++) {
            float4 a = *(float4*)&As[kc][ty * 4];
            float4 b = *(float4*)&Bs[kc][tx * 4];
            float aa[4] = {a.x, a.y, a.z, a.w};
            float bb[4] = {b.x, b.y, b.z, b.w};
            #pragma unroll
            for (int i = 0; i < 4; i++)
                #pragma unroll
                for (int j = 0; j < 4; j++)
                    acc[i][j] += aa[i] * bb[j];
        }
        __syncthreads();
    }
    int n = n0 + tx * 4;
    float4 bv = *(const float4*)&bias[n];
    #pragma unroll
    for (int i = 0; i < 4; i++) {
        int m = m0 + ty * 4 + i;
        float4 rv = *(const float4*)&resid[(size_t)m * CH + n];
        float4 v = make_float4(acc[i][0] + bv.x + rv.x,
                               acc[i][1] + bv.y + rv.y,
                               acc[i][2] + bv.z + rv.z,
                               acc[i][3] + bv.w + rv.w);
        *(float4*)&out[(size_t)m * CH + n] = v;
    }
}

// ---------------------------------------------------------------------------
extern "C" void kernel_launch(void* const* d_in, const int* in_sizes, int n_in,
                              void* d_out, int out_size) {
    const float* img   = (const float*)d_in[0];
    const float* gamma = (const float*)d_in[1];
    const float* beta  = (const float*)d_in[2];
    const float* w_qkv = (const float*)d_in[3];
    const float* w_out = (const float*)d_in[4];
    const float* b_out = (const float*)d_in[5];
    float* out = (float*)d_out;

    ln_kernel<<<TOK, 256>>>(img, gamma, beta);
    gemm_qkv_kernel<<<dim3(C3 / 64, TOK / 64), 256>>>(w_qkv);
    attn_kernel<<<dim3(SEQ / 64, BH), 256>>>();
    gemm_out_kernel<<<dim3(CH / 64, TOK / 64), 256>>>(w_out, b_out, img, out);
}

// round 10
// speedup vs baseline: 1.0453x; 1.0453x over previous

#include <cuda_runtime.h>
#include <math.h>

// Problem constants
#define BSZ 4
#define SEQ 2048
#define CH  768
#define NH  12
#define HD  64
#define TOK (BSZ*SEQ)   // 8192
#define C3  (3*CH)      // 2304
#define BH  (BSZ*NH)    // 48

// Scratch (allocation-free per harness rules)
__device__ float g_xn[TOK*CH];
__device__ float g_q[BH*SEQ*HD];
__device__ float g_k[BH*SEQ*HD];
__device__ float g_v[BH*SEQ*HD];
__device__ float g_att[TOK*CH];

// ---------------------------------------------------------------------------
// 1) LayerNorm: one block per token, 256 threads, 3 elems/thread
// ---------------------------------------------------------------------------
__global__ void ln_kernel(const float* __restrict__ x,
                          const float* __restrict__ gamma,
                          const float* __restrict__ beta) {
    int t = blockIdx.x;
    const float* xr = x + (size_t)t * CH;
    int i0 = threadIdx.x, i1 = i0 + 256, i2 = i0 + 512;
    float v0 = xr[i0], v1 = xr[i1], v2 = xr[i2];
    float s  = v0 + v1 + v2;
    float s2 = v0*v0 + v1*v1 + v2*v2;
    #pragma unroll
    for (int o = 16; o > 0; o >>= 1) {
        s  += __shfl_down_sync(0xffffffffu, s,  o);
        s2 += __shfl_down_sync(0xffffffffu, s2, o);
    }
    __shared__ float ws[8], ws2[8];
    __shared__ float mu_s, inv_s;
    int w = threadIdx.x >> 5, l = threadIdx.x & 31;
    if (l == 0) { ws[w] = s; ws2[w] = s2; }
    __syncthreads();
    if (threadIdx.x == 0) {
        float a = 0.f, b = 0.f;
        #pragma unroll
        for (int k = 0; k < 8; k++) { a += ws[k]; b += ws2[k]; }
        float mu  = a * (1.0f / CH);
        float var = b * (1.0f / CH) - mu * mu;
        mu_s  = mu;
        inv_s = rsqrtf(var + 1e-5f);
    }
    __syncthreads();
    float mu = mu_s, inv = inv_s;
    float* orow = g_xn + (size_t)t * CH;
    orow[i0] = (v0 - mu) * inv * gamma[i0] + beta[i0];
    orow[i1] = (v1 - mu) * inv * gamma[i1] + beta[i1];
    orow[i2] = (v2 - mu) * inv * gamma[i2] + beta[i2];
}

// ---------------------------------------------------------------------------
// 2) QKV GEMM: g_xn[8192,768] @ w_qkv[768,2304] -> head-major Q/K/V.
//    128x128x8 tile, 256 threads, 8x8 micro-tile, double-buffered smem.
// ---------------------------------------------------------------------------
__global__ void gemm_qkv_kernel(const float* __restrict__ W) {
    __shared__ float As[2][8][128];   // A^T [k][m]
    __shared__ float Bs[2][8][128];   // [k][n]

    int tid = threadIdx.x;
    int tx = tid & 15, ty = tid >> 4;
    int m0 = blockIdx.y * 128;
    int n0 = blockIdx.x * 128;

    float acc[8][8];
    #pragma unroll
    for (int i = 0; i < 8; i++)
        #pragma unroll
        for (int j = 0; j < 8; j++) acc[i][j] = 0.f;

    int ar = tid >> 1, ac = (tid & 1) * 4;   // A loader: one float4/thread
    int br = tid >> 5, bc = (tid & 31) * 4;  // B loader: one float4/thread

    // prologue: k-tile 0
    {
        float4 av = *(const float4*)&g_xn[(size_t)(m0 + ar) * CH + ac];
        As[0][ac+0][ar] = av.x; As[0][ac+1][ar] = av.y;
        As[0][ac+2][ar] = av.z; As[0][ac+3][ar] = av.w;
        *(float4*)&Bs[0][br][bc] = *(const float4*)&W[(size_t)br * C3 + n0 + bc];
    }
    __syncthreads();

    for (int kt = 0; kt < CH / 8; kt++) {
        int cur = kt & 1, nxt = cur ^ 1;
        float4 pa, pb;
        bool has_next = (kt + 1 < CH / 8);
        if (has_next) {
            int kb = (kt + 1) * 8;
            pa = *(const float4*)&g_xn[(size_t)(m0 + ar) * CH + kb + ac];
            pb = *(const float4*)&W[(size_t)(kb + br) * C3 + n0 + bc];
        }
        #pragma unroll
        for (int kk = 0; kk < 8; kk++) {
            float a[8], b[8];
            *(float4*)&a[0] = *(float4*)&As[cur][kk][ty * 8];
            *(float4*)&a[4] = *(float4*)&As[cur][kk][ty * 8 + 4];
            *(float4*)&b[0] = *(float4*)&Bs[cur][kk][tx * 8];
            *(float4*)&b[4] = *(float4*)&Bs[cur][kk][tx * 8 + 4];
            #pragma unroll
            for (int i = 0; i < 8; i++)
                #pragma unroll
                for (int j = 0; j < 8; j++)
                    acc[i][j] = fmaf(a[i], b[j], acc[i][j]);
        }
        if (has_next) {
            As[nxt][ac+0][ar] = pa.x; As[nxt][ac+1][ar] = pa.y;
            As[nxt][ac+2][ar] = pa.z; As[nxt][ac+3][ar] = pa.w;
            *(float4*)&Bs[nxt][br][bc] = pb;
        }
        __syncthreads();
    }

    // Epilogue: scatter to head-major q/k/v (per-thread column base)
    int nb    = n0 + tx * 8;
    int which = nb / CH;
    int h     = (nb % CH) >> 6;
    int d0    = nb & 63;           // 8 cols stay within one 64-wide head
    float* dst = (which == 0) ? g_q : ((which == 1) ? g_k : g_v);
    #pragma unroll
    for (int i = 0; i < 8; i++) {
        int m = m0 + ty * 8 + i;
        int b = m >> 11, nsq = m & (SEQ - 1);
        float* p = dst + ((size_t)(b * NH + h) * SEQ + nsq) * HD + d0;
        *(float4*)&p[0] = make_float4(acc[i][0], acc[i][1], acc[i][2], acc[i][3]);
        *(float4*)&p[4] = make_float4(acc[i][4], acc[i][5], acc[i][6], acc[i][7]);
    }
}

// ---------------------------------------------------------------------------
// 3) Flash attention: one block = 64 query rows of one (b,h).  (proven)
// ---------------------------------------------------------------------------
__global__ void attn_kernel() {
    __shared__ float QsT[64][64];  // [d][q]
    __shared__ float KPs[64][64];  // phase 1: K^T [d][kv]; phase 2: P [q][kv]
    __shared__ float Vs[64][64];   // [kv][d]

    int tid = threadIdx.x;
    int tx = tid & 15, ty = tid >> 4;
    int bh = blockIdx.y;
    int q0 = blockIdx.x * 64;
    const float scale = 0.125f;  // 1/sqrt(64)

    const float* Qg = g_q + (size_t)bh * SEQ * HD;
    const float* Kg = g_k + (size_t)bh * SEQ * HD;
    const float* Vg = g_v + (size_t)bh * SEQ * HD;

    int lr = tid >> 2;        // 0..63
    int lc = (tid & 3) * 16;  // 0,16,32,48

    // Load Q tile transposed + pre-scaled
    #pragma unroll
    for (int u = 0; u < 4; u++) {
        float4 v = *(const float4*)&Qg[(size_t)(q0 + lr) * HD + lc + u * 4];
        QsT[lc + u*4 + 0][lr] = v.x * scale;
        QsT[lc + u*4 + 1][lr] = v.y * scale;
        QsT[lc + u*4 + 2][lr] = v.z * scale;
        QsT[lc + u*4 + 3][lr] = v.w * scale;
    }

    float m_i[4], l_i[4], o[4][4];
    #pragma unroll
    for (int i = 0; i < 4; i++) {
        m_i[i] = -1e30f; l_i[i] = 0.f;
        #pragma unroll
        for (int j = 0; j < 4; j++) o[i][j] = 0.f;
    }

    for (int s0 = 0; s0 < SEQ; s0 += 64) {
        __syncthreads();  // previous iteration done reading KPs/Vs
        #pragma unroll
        for (int u = 0; u < 4; u++) {
            float4 kv = *(const float4*)&Kg[(size_t)(s0 + lr) * HD + lc + u * 4];
            KPs[lc + u*4 + 0][lr] = kv.x;
            KPs[lc + u*4 + 1][lr] = kv.y;
            KPs[lc + u*4 + 2][lr] = kv.z;
            KPs[lc + u*4 + 3][lr] = kv.w;
            float4 vv = *(const float4*)&Vg[(size_t)(s0 + lr) * HD + lc + u * 4];
            *(float4*)&Vs[lr][lc + u * 4] = vv;
        }
        __syncthreads();

        // S = Q K^T (scaled): 4x4 per thread, rows ty*4+i, cols tx*4+j
        float s[4][4] = {};
        #pragma unroll
        for (int d = 0; d < 64; d++) {
            float4 a = *(float4*)&QsT[d][ty * 4];
            float4 b = *(float4*)&KPs[d][tx * 4];
            float aa[4] = {a.x, a.y, a.z, a.w};
            float bb[4] = {b.x, b.y, b.z, b.w};
            #pragma unroll
            for (int i = 0; i < 4; i++)
                #pragma unroll
                for (int j = 0; j < 4; j++)
                    s[i][j] += aa[i] * bb[j];
        }

        // Online softmax. Row spread over 16 lanes (tx); shfl_xor 1..8 stays
        // in the 16-lane group since lane = (ty&1)*16 + tx.
        #pragma unroll
        for (int i = 0; i < 4; i++) {
            float mx = fmaxf(fmaxf(s[i][0], s[i][1]), fmaxf(s[i][2], s[i][3]));
            #pragma unroll
            for (int off = 8; off > 0; off >>= 1)
                mx = fmaxf(mx, __shfl_xor_sync(0xffffffffu, mx, off));
            float mnew = fmaxf(m_i[i], mx);
            float f = __expf(m_i[i] - mnew);
            float rs = 0.f;
            #pragma unroll
            for (int j = 0; j < 4; j++) {
                s[i][j] = __expf(s[i][j] - mnew);
                rs += s[i][j];
            }
            #pragma unroll
            for (int off = 8; off > 0; off >>= 1)
                rs += __shfl_xor_sync(0xffffffffu, rs, off);
            l_i[i] = l_i[i] * f + rs;
            m_i[i] = mnew;
            #pragma unroll
            for (int j = 0; j < 4; j++) o[i][j] *= f;
        }

        __syncthreads();  // done reading KPs as K
        // Write P row-major: P[q][kv]
        #pragma unroll
        for (int i = 0; i < 4; i++)
            #pragma unroll
            for (int j = 0; j < 4; j++)
                KPs[ty * 4 + i][tx * 4 + j] = s[i][j];
        __syncthreads();

        // O += P @ V  (kv tiled by 4 for vector loads)
        #pragma unroll
        for (int kk0 = 0; kk0 < 16; kk0++) {
            float4 bv[4];
            #pragma unroll
            for (int u = 0; u < 4; u++)
                bv[u] = *(float4*)&Vs[kk0 * 4 + u][tx * 4];
            #pragma unroll
            for (int i = 0; i < 4; i++) {
                float4 a = *(float4*)&KPs[ty * 4 + i][kk0 * 4];
                float aa[4] = {a.x, a.y, a.z, a.w};
                #pragma unroll
                for (int u = 0; u < 4; u++) {
                    float bb[4] = {bv[u].x, bv[u].y, bv[u].z, bv[u].w};
                    #pragma unroll
                    for (int j = 0; j < 4; j++)
                        o[i][j] += aa[u] * bb[j];
                }
            }
        }
    }

    // Epilogue: normalize, write token-major [B,N,C]
    int b = bh / NH, h = bh % NH;
    #pragma unroll
    for (int i = 0; i < 4; i++) {
        int r = q0 + ty * 4 + i;
        float invl = 1.0f / l_i[i];
        float4 v = make_float4(o[i][0]*invl, o[i][1]*invl, o[i][2]*invl, o[i][3]*invl);
        *(float4*)&g_att[((size_t)(b * SEQ + r)) * CH + h * HD + tx * 4] = v;
    }
}

// ---------------------------------------------------------------------------
// 4) Output GEMM + bias + residual: g_att[8192,768] @ w_out[768,768].
//    128x128x8 tile, 256 threads, 8x8 micro-tile, double-buffered smem.
// ---------------------------------------------------------------------------
__global__ void gemm_out_kernel(const float* __restrict__ W,
                                const float* __restrict__ bias,
                                const float* __restrict__ resid,
                                float* __restrict__ out) {
    __shared__ float As[2][8][128];
    __shared__ float Bs[2][8][128];

    int tid = threadIdx.x;
    int tx = tid & 15, ty = tid >> 4;
    int m0 = blockIdx.y * 128;
    int n0 = blockIdx.x * 128;

    float acc[8][8];
    #pragma unroll
    for (int i = 0; i < 8; i++)
        #pragma unroll
        for (int j = 0; j < 8; j++) acc[i][j] = 0.f;

    int ar = tid >> 1, ac = (tid & 1) * 4;
    int br = tid >> 5, bc = (tid & 31) * 4;

    {
        float4 av = *(const float4*)&g_att[(size_t)(m0 + ar) * CH + ac];
        As[0][ac+0][ar] = av.x; As[0][ac+1][ar] = av.y;
        As[0][ac+2][ar] = av.z; As[0][ac+3][ar] = av.w;
        *(float4*)&Bs[0][br][bc] = *(const float4*)&W[(size_t)br * CH + n0 + bc];
    }
    __syncthreads();

    for (int kt = 0; kt < CH / 8; kt++) {
        int cur = kt & 1, nxt = cur ^ 1;
        float4 pa, pb;
        bool has_next = (kt + 1 < CH / 8);
        if (has_next) {
            int kb = (kt + 1) * 8;
            pa = *(const float4*)&g_att[(size_t)(m0 + ar) * CH + kb + ac];
            pb = *(const float4*)&W[(size_t)(kb + br) * CH + n0 + bc];
        }
        #pragma unroll
        for (int kk = 0; kk < 8; kk++) {
            float a[8], b[8];
            *(float4*)&a[0] = *(float4*)&As[cur][kk][ty * 8];
            *(float4*)&a[4] = *(float4*)&As[cur][kk][ty * 8 + 4];
            *(float4*)&b[0] = *(float4*)&Bs[cur][kk][tx * 8];
            *(float4*)&b[4] = *(float4*)&Bs[cur][kk][tx * 8 + 4];
            #pragma unroll
            for (int i = 0; i < 8; i++)
                #pragma unroll
                for (int j = 0; j < 8; j++)
                    acc[i][j] = fmaf(a[i], b[j], acc[i][j]);
        }
        if (has_next) {
            As[nxt][ac+0][ar] = pa.x; As[nxt][ac+1][ar] = pa.y;
            As[nxt][ac+2][ar] = pa.z; As[nxt][ac+3][ar] = pa.w;
            *(float4*)&Bs[nxt][br][bc] = pb;
        }
        __syncthreads();
    }

    int n = n0 + tx * 8;
    float4 bv0 = *(const float4*)&bias[n];
    float4 bv1 = *(const float4*)&bias[n + 4];
    #pragma unroll
    for (int i = 0; i < 8; i++) {
        int m = m0 + ty * 8 + i;
        float4 r0 = *(const float4*)&resid[(size_t)m * CH + n];
        float4 r1 = *(const float4*)&resid[(size_t)m * CH + n + 4];
        float* p = out + (size_t)m * CH + n;
        *(float4*)&p[0] = make_float4(acc[i][0] + bv0.x + r0.x,
                                      acc[i][1] + bv0.y + r0.y,
                                      acc[i][2] + bv0.z + r0.z,
                                      acc[i][3] + bv0.w + r0.w);
        *(float4*)&p[4] = make_float4(acc[i][4] + bv1.x + r1.x,
                                      acc[i][5] + bv1.y + r1.y,
                                      acc[i][6] + bv1.z + r1.z,
                                      acc[i][7] + bv1.w + r1.w);
    }
}

// ---------------------------------------------------------------------------
extern "C" void kernel_launch(void* const* d_in, const int* in_sizes, int n_in,
                              void* d_out, int out_size) {
    const float* img   = (const float*)d_in[0];
    const float* gamma = (const float*)d_in[1];
    const float* beta  = (const float*)d_in[2];
    const float* w_qkv = (const float*)d_in[3];
    const float* w_out = (const float*)d_in[4];
    const float* b_out = (const float*)d_in[5];
    float* out = (float*)d_out;

    ln_kernel<<<TOK, 256>>>(img, gamma, beta);
    gemm_qkv_kernel<<<dim3(C3 / 128, TOK / 128), 256>>>(w_qkv);
    attn_kernel<<<dim3(SEQ / 64, BH), 256>>>();
    gemm_out_kernel<<<dim3(CH / 128, TOK / 128), 256>>>(w_out, b_out, img, out);
}

// round 11
// speedup vs baseline: 2.2687x; 2.1704x over previous

#include <cuda_runtime.h>
#include <cuda_fp16.h>
#include <math.h>
#include <stdint.h>

// Problem constants
#define BSZ 4
#define SEQ 2048
#define CH  768
#define NH  12
#define HD  64
#define TOK (BSZ*SEQ)   // 8192
#define C3  (3*CH)      // 2304
#define BH  (BSZ*NH)    // 48

// Scratch (allocation-free per harness rules)
__device__ float g_xn[TOK*CH];
__device__ float g_q[BH*SEQ*HD];
__device__ float g_k[BH*SEQ*HD];
__device__ float g_v[BH*SEQ*HD];
__device__ float g_att[TOK*CH];

// ---------------------------------------------------------------------------
// fp16 split + mma helpers
// ---------------------------------------------------------------------------
__device__ __forceinline__ void splitf(float x, __half& h, __half& l) {
    h = __float2half_rn(x);
    l = __float2half_rn(x - __half2float(h));
}

__device__ __forceinline__ void ldsm4(uint32_t a[4], const void* p) {
    uint32_t addr = (uint32_t)__cvta_generic_to_shared(p);
    asm volatile("ldmatrix.sync.aligned.m8n8.x4.shared.b16 {%0,%1,%2,%3}, [%4];"
                 : "=r"(a[0]), "=r"(a[1]), "=r"(a[2]), "=r"(a[3]) : "r"(addr));
}

__device__ __forceinline__ void ldsm4t(uint32_t a[4], const void* p) {
    uint32_t addr = (uint32_t)__cvta_generic_to_shared(p);
    asm volatile("ldmatrix.sync.aligned.m8n8.x4.trans.shared.b16 {%0,%1,%2,%3}, [%4];"
                 : "=r"(a[0]), "=r"(a[1]), "=r"(a[2]), "=r"(a[3]) : "r"(addr));
}

__device__ __forceinline__ void mma_f16(float c[4], const uint32_t a[4], const uint32_t b[2]) {
    asm volatile(
        "mma.sync.aligned.m16n8k16.row.col.f32.f16.f16.f32 "
        "{%0,%1,%2,%3},{%4,%5,%6,%7},{%8,%9},{%0,%1,%2,%3};"
        : "+f"(c[0]), "+f"(c[1]), "+f"(c[2]), "+f"(c[3])
        : "r"(a[0]), "r"(a[1]), "r"(a[2]), "r"(a[3]), "r"(b[0]), "r"(b[1]));
}

// ---------------------------------------------------------------------------
// 1) LayerNorm: one block per token, 256 threads, 3 elems/thread (proven)
// ---------------------------------------------------------------------------
__global__ void ln_kernel(const float* __restrict__ x,
                          const float* __restrict__ gamma,
                          const float* __restrict__ beta) {
    int t = blockIdx.x;
    const float* xr = x + (size_t)t * CH;
    int i0 = threadIdx.x, i1 = i0 + 256, i2 = i0 + 512;
    float v0 = xr[i0], v1 = xr[i1], v2 = xr[i2];
    float s  = v0 + v1 + v2;
    float s2 = v0*v0 + v1*v1 + v2*v2;
    #pragma unroll
    for (int o = 16; o > 0; o >>= 1) {
        s  += __shfl_down_sync(0xffffffffu, s,  o);
        s2 += __shfl_down_sync(0xffffffffu, s2, o);
    }
    __shared__ float ws[8], ws2[8];
    __shared__ float mu_s, inv_s;
    int w = threadIdx.x >> 5, l = threadIdx.x & 31;
    if (l == 0) { ws[w] = s; ws2[w] = s2; }
    __syncthreads();
    if (threadIdx.x == 0) {
        float a = 0.f, b = 0.f;
        #pragma unroll
        for (int k = 0; k < 8; k++) { a += ws[k]; b += ws2[k]; }
        float mu  = a * (1.0f / CH);
        float var = b * (1.0f / CH) - mu * mu;
        mu_s  = mu;
        inv_s = rsqrtf(var + 1e-5f);
    }
    __syncthreads();
    float mu = mu_s, inv = inv_s;
    float* orow = g_xn + (size_t)t * CH;
    orow[i0] = (v0 - mu) * inv * gamma[i0] + beta[i0];
    orow[i1] = (v1 - mu) * inv * gamma[i1] + beta[i1];
    orow[i2] = (v2 - mu) * inv * gamma[i2] + beta[i2];
}

// ---------------------------------------------------------------------------
// Shared GEMM config: BM=128, BN=64, BK=16, 128 threads = 4 warps (2x2),
// warp tile 64x32. A x8, W x64 before hi/lo split; epilogue x (1/512).
// ---------------------------------------------------------------------------
#define GBM 128
#define GBN 64
#define GBK 16
#define HPAD 24
#define ASCALE 8.0f
#define WSCALE 64.0f
#define CINV   (1.0f/512.0f)

// 2) QKV GEMM (fp16x3): g_xn @ w_qkv -> head-major Q/K/V
__global__ void f16gemm_qkv(const float* __restrict__ B) {
    __shared__ __half Ah[2][GBM][HPAD], Al[2][GBM][HPAD];
    __shared__ __half Bh[2][GBN][HPAD], Bl[2][GBN][HPAD];

    int tid = threadIdx.x;
    int w = tid >> 5, L = tid & 31;
    int wm = w >> 1, wn = w & 1;
    int m0 = blockIdx.y * GBM;
    int n0 = blockIdx.x * GBN;

    float acc[4][4][4];
    #pragma unroll
    for (int i = 0; i < 4; i++)
        #pragma unroll
        for (int j = 0; j < 4; j++)
            #pragma unroll
            for (int c = 0; c < 4; c++) acc[i][j][c] = 0.f;

    int b_n  = tid & 63;
    int b_k0 = (tid >> 6) * 8;
    const int KT = CH / GBK;

    {
        #pragma unroll
        for (int i = 0; i < 4; i++) {
            int s = tid + i * 128;
            int r = s >> 2, c = (s & 3) * 4;
            float4 v = *(const float4*)(g_xn + (size_t)(m0 + r) * CH + c);
            __half h, lo;
            splitf(v.x * ASCALE, h, lo); Ah[0][r][c+0] = h; Al[0][r][c+0] = lo;
            splitf(v.y * ASCALE, h, lo); Ah[0][r][c+1] = h; Al[0][r][c+1] = lo;
            splitf(v.z * ASCALE, h, lo); Ah[0][r][c+2] = h; Al[0][r][c+2] = lo;
            splitf(v.w * ASCALE, h, lo); Ah[0][r][c+3] = h; Al[0][r][c+3] = lo;
        }
        #pragma unroll
        for (int j = 0; j < 8; j++) {
            float wv = B[(size_t)(b_k0 + j) * C3 + n0 + b_n] * WSCALE;
            __half h, lo;
            splitf(wv, h, lo);
            Bh[0][b_n][b_k0 + j] = h; Bl[0][b_n][b_k0 + j] = lo;
        }
    }
    __syncthreads();

    int a_row_off = ((L >> 3) & 1) * 8 + (L & 7);
    int a_col_off = ((L >> 4) & 1) * 8;
    int b_n_off   = ((L >> 4) & 1) * 8 + (L & 7);
    int b_k_off   = ((L >> 3) & 1) * 8;

    for (int kt = 0; kt < KT; kt++) {
        int cur = kt & 1, nxt = cur ^ 1;
        float4 pa[4]; float pb[8];
        bool has_next = (kt + 1 < KT);
        if (has_next) {
            int kbase = (kt + 1) * GBK;
            #pragma unroll
            for (int i = 0; i < 4; i++) {
                int s = tid + i * 128;
                int r = s >> 2, c = (s & 3) * 4;
                pa[i] = *(const float4*)(g_xn + (size_t)(m0 + r) * CH + kbase + c);
            }
            #pragma unroll
            for (int j = 0; j < 8; j++)
                pb[j] = B[(size_t)(kbase + b_k0 + j) * C3 + n0 + b_n];
        }
        {
            uint32_t afh[4][4], afl[4][4];
            #pragma unroll
            for (int mf = 0; mf < 4; mf++) {
                int row = wm * 64 + mf * 16 + a_row_off;
                ldsm4(afh[mf], &Ah[cur][row][a_col_off]);
                ldsm4(afl[mf], &Al[cur][row][a_col_off]);
            }
            #pragma unroll
            for (int p = 0; p < 2; p++) {
                int n = wn * 32 + p * 16 + b_n_off;
                uint32_t th[4], tl[4];
                ldsm4(th, &Bh[cur][n][b_k_off]);
                ldsm4(tl, &Bl[cur][n][b_k_off]);
                #pragma unroll
                for (int q = 0; q < 2; q++) {
                    int nf = 2 * p + q;
                    const uint32_t bh2[2] = {th[2*q], th[2*q+1]};
                    const uint32_t bl2[2] = {tl[2*q], tl[2*q+1]};
                    #pragma unroll
                    for (int mf = 0; mf < 4; mf++) {
                        mma_f16(acc[mf][nf], afh[mf], bh2);
                        mma_f16(acc[mf][nf], afh[mf], bl2);
                        mma_f16(acc[mf][nf], afl[mf], bh2);
                    }
                }
            }
        }
        if (has_next) {
            #pragma unroll
            for (int i = 0; i < 4; i++) {
                int s = tid + i * 128;
                int r = s >> 2, c = (s & 3) * 4;
                __half h, lo;
                splitf(pa[i].x * ASCALE, h, lo); Ah[nxt][r][c+0] = h; Al[nxt][r][c+0] = lo;
                splitf(pa[i].y * ASCALE, h, lo); Ah[nxt][r][c+1] = h; Al[nxt][r][c+1] = lo;
                splitf(pa[i].z * ASCALE, h, lo); Ah[nxt][r][c+2] = h; Al[nxt][r][c+2] = lo;
                splitf(pa[i].w * ASCALE, h, lo); Ah[nxt][r][c+3] = h; Al[nxt][r][c+3] = lo;
            }
            #pragma unroll
            for (int j = 0; j < 8; j++) {
                __half h, lo;
                splitf(pb[j] * WSCALE, h, lo);
                Bh[nxt][b_n][b_k0 + j] = h; Bl[nxt][b_n][b_k0 + j] = lo;
            }
        }
        __syncthreads();
    }

    int g = L >> 2, t2 = (L & 3) * 2;
    int which = n0 / CH;
    int h = (n0 % CH) >> 6;
    float* dst = (which == 0) ? g_q : ((which == 1) ? g_k : g_v);
    #pragma unroll
    for (int mf = 0; mf < 4; mf++)
        #pragma unroll
        for (int nf = 0; nf < 4; nf++) {
            int d = wn * 32 + nf * 8 + t2;
            #pragma unroll
            for (int half = 0; half < 2; half++) {
                int m = m0 + wm * 64 + mf * 16 + g + half * 8;
                int b = m >> 11, n = m & (SEQ - 1);
                float2 v = make_float2(acc[mf][nf][half*2]   * CINV,
                                       acc[mf][nf][half*2+1] * CINV);
                *(float2*)&dst[((size_t)(b * NH + h) * SEQ + n) * HD + d] = v;
            }
        }
}

// 4) Output GEMM (fp16x3): g_att @ w_out + bias + residual
__global__ void f16gemm_out(const float* __restrict__ B,
                            const float* __restrict__ bias,
                            const float* __restrict__ resid,
                            float* __restrict__ outp) {
    __shared__ __half Ah[2][GBM][HPAD], Al[2][GBM][HPAD];
    __shared__ __half Bh[2][GBN][HPAD], Bl[2][GBN][HPAD];

    int tid = threadIdx.x;
    int w = tid >> 5, L = tid & 31;
    int wm = w >> 1, wn = w & 1;
    int m0 = blockIdx.y * GBM;
    int n0 = blockIdx.x * GBN;

    float acc[4][4][4];
    #pragma unroll
    for (int i = 0; i < 4; i++)
        #pragma unroll
        for (int j = 0; j < 4; j++)
            #pragma unroll
            for (int c = 0; c < 4; c++) acc[i][j][c] = 0.f;

    int b_n  = tid & 63;
    int b_k0 = (tid >> 6) * 8;
    const int KT = CH / GBK;

    {
        #pragma unroll
        for (int i = 0; i < 4; i++) {
            int s = tid + i * 128;
            int r = s >> 2, c = (s & 3) * 4;
            float4 v = *(const float4*)(g_att + (size_t)(m0 + r) * CH + c);
            __half h, lo;
            splitf(v.x * ASCALE, h, lo); Ah[0][r][c+0] = h; Al[0][r][c+0] = lo;
            splitf(v.y * ASCALE, h, lo); Ah[0][r][c+1] = h; Al[0][r][c+1] = lo;
            splitf(v.z * ASCALE, h, lo); Ah[0][r][c+2] = h; Al[0][r][c+2] = lo;
            splitf(v.w * ASCALE, h, lo); Ah[0][r][c+3] = h; Al[0][r][c+3] = lo;
        }
        #pragma unroll
        for (int j = 0; j < 8; j++) {
            float wv = B[(size_t)(b_k0 + j) * CH + n0 + b_n] * WSCALE;
            __half h, lo;
            splitf(wv, h, lo);
            Bh[0][b_n][b_k0 + j] = h; Bl[0][b_n][b_k0 + j] = lo;
        }
    }
    __syncthreads();

    int a_row_off = ((L >> 3) & 1) * 8 + (L & 7);
    int a_col_off = ((L >> 4) & 1) * 8;
    int b_n_off   = ((L >> 4) & 1) * 8 + (L & 7);
    int b_k_off   = ((L >> 3) & 1) * 8;

    for (int kt = 0; kt < KT; kt++) {
        int cur = kt & 1, nxt = cur ^ 1;
        float4 pa[4]; float pb[8];
        bool has_next = (kt + 1 < KT);
        if (has_next) {
            int kbase = (kt + 1) * GBK;
            #pragma unroll
            for (int i = 0; i < 4; i++) {
                int s = tid + i * 128;
                int r = s >> 2, c = (s & 3) * 4;
                pa[i] = *(const float4*)(g_att + (size_t)(m0 + r) * CH + kbase + c);
            }
            #pragma unroll
            for (int j = 0; j < 8; j++)
                pb[j] = B[(size_t)(kbase + b_k0 + j) * CH + n0 + b_n];
        }
        {
            uint32_t afh[4][4], afl[4][4];
            #pragma unroll
            for (int mf = 0; mf < 4; mf++) {
                int row = wm * 64 + mf * 16 + a_row_off;
                ldsm4(afh[mf], &Ah[cur][row][a_col_off]);
                ldsm4(afl[mf], &Al[cur][row][a_col_off]);
            }
            #pragma unroll
            for (int p = 0; p < 2; p++) {
                int n = wn * 32 + p * 16 + b_n_off;
                uint32_t th[4], tl[4];
                ldsm4(th, &Bh[cur][n][b_k_off]);
                ldsm4(tl, &Bl[cur][n][b_k_off]);
                #pragma unroll
                for (int q = 0; q < 2; q++) {
                    int nf = 2 * p + q;
                    const uint32_t bh2[2] = {th[2*q], th[2*q+1]};
                    const uint32_t bl2[2] = {tl[2*q], tl[2*q+1]};
                    #pragma unroll
                    for (int mf = 0; mf < 4; mf++) {
                        mma_f16(acc[mf][nf], afh[mf], bh2);
                        mma_f16(acc[mf][nf], afh[mf], bl2);
                        mma_f16(acc[mf][nf], afl[mf], bh2);
                    }
                }
            }
        }
        if (has_next) {
            #pragma unroll
            for (int i = 0; i < 4; i++) {
                int s = tid + i * 128;
                int r = s >> 2, c = (s & 3) * 4;
                __half h, lo;
                splitf(pa[i].x * ASCALE, h, lo); Ah[nxt][r][c+0] = h; Al[nxt][r][c+0] = lo;
                splitf(pa[i].y * ASCALE, h, lo); Ah[nxt][r][c+1] = h; Al[nxt][r][c+1] = lo;
                splitf(pa[i].z * ASCALE, h, lo); Ah[nxt][r][c+2] = h; Al[nxt][r][c+2] = lo;
                splitf(pa[i].w * ASCALE, h, lo); Ah[nxt][r][c+3] = h; Al[nxt][r][c+3] = lo;
            }
            #pragma unroll
            for (int j = 0; j < 8; j++) {
                __half h, lo;
                splitf(pb[j] * WSCALE, h, lo);
                Bh[nxt][b_n][b_k0 + j] = h; Bl[nxt][b_n][b_k0 + j] = lo;
            }
        }
        __syncthreads();
    }

    int g = L >> 2, t2 = (L & 3) * 2;
    #pragma unroll
    for (int mf = 0; mf < 4; mf++)
        #pragma unroll
        for (int nf = 0; nf < 4; nf++) {
            int col = n0 + wn * 32 + nf * 8 + t2;
            float2 bv = *(const float2*)&bias[col];
            #pragma unroll
            for (int half = 0; half < 2; half++) {
                int m = m0 + wm * 64 + mf * 16 + g + half * 8;
                float2 rv = *(const float2*)&resid[(size_t)m * CH + col];
                float2 v = make_float2(acc[mf][nf][half*2]   * CINV + bv.x + rv.x,
                                       acc[mf][nf][half*2+1] * CINV + bv.y + rv.y);
                *(float2*)&outp[(size_t)m * CH + col] = v;
            }
        }
}

// ---------------------------------------------------------------------------
// 3) Flash attention, fp16x3 mma. Block = 64 q rows of one (b,h), 4 warps.
//    Q,K,V x8 at split; S x 0.125/64 after mma; P x64 at split; O /(512 l).
// ---------------------------------------------------------------------------
#define APAD 72
#define SMUL (0.125f/64.0f)
#define OINV_SCALE (1.0f/512.0f)

__global__ void f16attn() {
    __shared__ __half Kh[64][APAD], Kl[64][APAD];
    __shared__ __half Vh[64][APAD], Vl[64][APAD];

    int tid = threadIdx.x;
    int w = tid >> 5, L = tid & 31;
    int bh = blockIdx.y;
    int q0 = blockIdx.x * 64;

    const float* Qg = g_q + (size_t)bh * SEQ * HD;
    const float* Kg = g_k + (size_t)bh * SEQ * HD;
    const float* Vg = g_v + (size_t)bh * SEQ * HD;

    int a_row_off = ((L >> 3) & 1) * 8 + (L & 7);
    int a_col_off = ((L >> 4) & 1) * 8;
    int b_n_off   = ((L >> 4) & 1) * 8 + (L & 7);
    int b_k_off   = ((L >> 3) & 1) * 8;
    int g = L >> 2, t2 = (L & 3) * 2;

    // Stage Q (x8) through Kh/Kl, build persistent fragments
    #pragma unroll
    for (int i = 0; i < 8; i++) {
        int s = tid + i * 128;
        int r = s >> 4, d4 = (s & 15) * 4;
        float4 v = *(const float4*)&Qg[(size_t)(q0 + r) * HD + d4];
        __half h, lo;
        splitf(v.x * 8.0f, h, lo); Kh[r][d4+0] = h; Kl[r][d4+0] = lo;
        splitf(v.y * 8.0f, h, lo); Kh[r][d4+1] = h; Kl[r][d4+1] = lo;
        splitf(v.z * 8.0f, h, lo); Kh[r][d4+2] = h; Kl[r][d4+2] = lo;
        splitf(v.w * 8.0f, h, lo); Kh[r][d4+3] = h; Kl[r][d4+3] = lo;
    }
    __syncthreads();
    uint32_t qfh[4][4], qfl[4][4];
    #pragma unroll
    for (int ks = 0; ks < 4; ks++) {
        int row = w * 16 + a_row_off;
        ldsm4(qfh[ks], &Kh[row][ks * 16 + a_col_off]);
        ldsm4(qfl[ks], &Kl[row][ks * 16 + a_col_off]);
    }

    float m0r = -1e30f, m1r = -1e30f, l0 = 0.f, l1 = 0.f;
    float oacc[8][4];
    #pragma unroll
    for (int j = 0; j < 8; j++)
        #pragma unroll
        for (int c = 0; c < 4; c++) oacc[j][c] = 0.f;

    for (int s0 = 0; s0 < SEQ; s0 += 64) {
        __syncthreads();
        // Load K and V tiles [kv][d] (x8), split hi/lo
        #pragma unroll
        for (int i = 0; i < 8; i++) {
            int s = tid + i * 128;
            int kv = s >> 4, d4 = (s & 15) * 4;
            float4 kvv = *(const float4*)&Kg[(size_t)(s0 + kv) * HD + d4];
            __half h, lo;
            splitf(kvv.x * 8.0f, h, lo); Kh[kv][d4+0] = h; Kl[kv][d4+0] = lo;
            splitf(kvv.y * 8.0f, h, lo); Kh[kv][d4+1] = h; Kl[kv][d4+1] = lo;
            splitf(kvv.z * 8.0f, h, lo); Kh[kv][d4+2] = h; Kl[kv][d4+2] = lo;
            splitf(kvv.w * 8.0f, h, lo); Kh[kv][d4+3] = h; Kl[kv][d4+3] = lo;
            float4 vv = *(const float4*)&Vg[(size_t)(s0 + kv) * HD + d4];
            splitf(vv.x * 8.0f, h, lo); Vh[kv][d4+0] = h; Vl[kv][d4+0] = lo;
            splitf(vv.y * 8.0f, h, lo); Vh[kv][d4+1] = h; Vl[kv][d4+1] = lo;
            splitf(vv.z * 8.0f, h, lo); Vh[kv][d4+2] = h; Vl[kv][d4+2] = lo;
            splitf(vv.w * 8.0f, h, lo); Vh[kv][d4+3] = h; Vl[kv][d4+3] = lo;
        }
        __syncthreads();

        // S = (8Q)(8K)^T ; rescale by 0.125/64 after
        float sacc[8][4];
        #pragma unroll
        for (int j = 0; j < 8; j++)
            #pragma unroll
            for (int c = 0; c < 4; c++) sacc[j][c] = 0.f;
        #pragma unroll
        for (int ks = 0; ks < 4; ks++) {
            #pragma unroll
            for (int p = 0; p < 4; p++) {
                int n = p * 16 + b_n_off;
                uint32_t th[4], tl[4];
                ldsm4(th, &Kh[n][ks * 16 + b_k_off]);
                ldsm4(tl, &Kl[n][ks * 16 + b_k_off]);
                #pragma unroll
                for (int q = 0; q < 2; q++) {
                    int j = 2 * p + q;
                    const uint32_t bh2[2] = {th[2*q], th[2*q+1]};
                    const uint32_t bl2[2] = {tl[2*q], tl[2*q+1]};
                    mma_f16(sacc[j], qfh[ks], bh2);
                    mma_f16(sacc[j], qfh[ks], bl2);
                    mma_f16(sacc[j], qfl[ks], bh2);
                }
            }
        }
        #pragma unroll
        for (int j = 0; j < 8; j++)
            #pragma unroll
            for (int c = 0; c < 4; c++) sacc[j][c] *= SMUL;

        // Online softmax on fragments (rows g and g+8 of this warp's 16)
        float mx0 = -1e30f, mx1 = -1e30f;
        #pragma unroll
        for (int j = 0; j < 8; j++) {
            mx0 = fmaxf(mx0, fmaxf(sacc[j][0], sacc[j][1]));
            mx1 = fmaxf(mx1, fmaxf(sacc[j][2], sacc[j][3]));
        }
        #pragma unroll
        for (int o = 1; o <= 2; o <<= 1) {
            mx0 = fmaxf(mx0, __shfl_xor_sync(0xffffffffu, mx0, o));
            mx1 = fmaxf(mx1, __shfl_xor_sync(0xffffffffu, mx1, o));
        }
        float mn0 = fmaxf(m0r, mx0), mn1 = fmaxf(m1r, mx1);
        float f0 = __expf(m0r - mn0), f1 = __expf(m1r - mn1);
        m0r = mn0; m1r = mn1;
        float rs0 = 0.f, rs1 = 0.f;
        #pragma unroll
        for (int j = 0; j < 8; j++) {
            sacc[j][0] = __expf(sacc[j][0] - mn0);
            sacc[j][1] = __expf(sacc[j][1] - mn0);
            sacc[j][2] = __expf(sacc[j][2] - mn1);
            sacc[j][3] = __expf(sacc[j][3] - mn1);
            rs0 += sacc[j][0] + sacc[j][1];
            rs1 += sacc[j][2] + sacc[j][3];
        }
        #pragma unroll
        for (int o = 1; o <= 2; o <<= 1) {
            rs0 += __shfl_xor_sync(0xffffffffu, rs0, o);
            rs1 += __shfl_xor_sync(0xffffffffu, rs1, o);
        }
        l0 = l0 * f0 + rs0;
        l1 = l1 * f1 + rs1;
        #pragma unroll
        for (int j = 0; j < 8; j++) {
            oacc[j][0] *= f0; oacc[j][1] *= f0;
            oacc[j][2] *= f1; oacc[j][3] *= f1;
        }

        __syncthreads();
        // Write P (x64) split into Kh/Kl as [q][kv]
        #pragma unroll
        for (int j = 0; j < 8; j++) {
            int c0 = j * 8 + t2;
            __half h0, l0h, h1, l1h;
            splitf(sacc[j][0] * 64.0f, h0, l0h); splitf(sacc[j][1] * 64.0f, h1, l1h);
            *(__half2*)&Kh[w*16 + g][c0] = __halves2half2(h0, h1);
            *(__half2*)&Kl[w*16 + g][c0] = __halves2half2(l0h, l1h);
            splitf(sacc[j][2] * 64.0f, h0, l0h); splitf(sacc[j][3] * 64.0f, h1, l1h);
            *(__half2*)&Kh[w*16 + g + 8][c0] = __halves2half2(h0, h1);
            *(__half2*)&Kl[w*16 + g + 8][c0] = __halves2half2(l0h, l1h);
        }
        __syncthreads();

        // O += (64P)(8V)   (V via ldmatrix.trans)
        #pragma unroll
        for (int ks = 0; ks < 4; ks++) {
            uint32_t pah[4], pal[4];
            int row = w * 16 + a_row_off;
            ldsm4(pah, &Kh[row][ks * 16 + a_col_off]);
            ldsm4(pal, &Kl[row][ks * 16 + a_col_off]);
            #pragma unroll
            for (int p = 0; p < 4; p++) {
                uint32_t th[4], tl[4];
                ldsm4t(th, &Vh[ks * 16 + a_row_off][p * 16 + a_col_off]);
                ldsm4t(tl, &Vl[ks * 16 + a_row_off][p * 16 + a_col_off]);
                #pragma unroll
                for (int q = 0; q < 2; q++) {
                    int j = 2 * p + q;
                    const uint32_t bh2[2] = {th[2*q], th[2*q+1]};
                    const uint32_t bl2[2] = {tl[2*q], tl[2*q+1]};
                    mma_f16(oacc[j], pah, bh2);
                    mma_f16(oacc[j], pah, bl2);
                    mma_f16(oacc[j], pal, bh2);
                }
            }
        }
    }

    // Epilogue: normalize (undo 512x), write token-major [B,N,C]
    int b = bh / NH, h = bh % NH;
    float inv0 = OINV_SCALE / l0, inv1 = OINV_SCALE / l1;
    #pragma unroll
    for (int j = 0; j < 8; j++) {
        int d = j * 8 + t2;
        int q = q0 + w * 16 + g;
        *(float2*)&g_att[((size_t)(b * SEQ + q)) * CH + h * HD + d] =
            make_float2(oacc[j][0] * inv0, oacc[j][1] * inv0);
        *(float2*)&g_att[((size_t)(b * SEQ + q + 8)) * CH + h * HD + d] =
            make_float2(oacc[j][2] * inv1, oacc[j][3] * inv1);
    }
}

// ---------------------------------------------------------------------------
extern "C" void kernel_launch(void* const* d_in, const int* in_sizes, int n_in,
                              void* d_out, int out_size) {
    const float* img   = (const float*)d_in[0];
    const float* gamma = (const float*)d_in[1];
    const float* beta  = (const float*)d_in[2];
    const float* w_qkv = (const float*)d_in[3];
    const float* w_out = (const float*)d_in[4];
    const float* b_out = (const float*)d_in[5];
    float* out = (float*)d_out;

    ln_kernel<<<TOK, 256>>>(img, gamma, beta);
    f16gemm_qkv<<<dim3(C3 / GBN, TOK / GBM), 128>>>(w_qkv);
    f16attn<<<dim3(SEQ / 64, BH), 128>>>();
    f16gemm_out<<<dim3(CH / GBN, TOK / GBM), 128>>>(w_out, b_out, img, out);
}

// round 12
// speedup vs baseline: 2.3782x; 1.0482x over previous

#include <cuda_runtime.h>
#include <cuda_fp16.h>
#include <math.h>
#include <stdint.h>

// Problem constants
#define BSZ 4
#define SEQ 2048
#define CH  768
#define NH  12
#define HD  64
#define TOK (BSZ*SEQ)   // 8192
#define C3  (3*CH)      // 2304
#define BH  (BSZ*NH)    // 48

// Pre-split hi/lo half storage (allocation-free per harness rules)
__device__ __half g_xnh[TOK*CH],  g_xnl[TOK*CH];     // LN output, x8
__device__ __half g_qh[BH*SEQ*HD], g_ql[BH*SEQ*HD];  // Q, x8
__device__ __half g_kh[BH*SEQ*HD], g_kl[BH*SEQ*HD];  // K, x8
__device__ __half g_vh[BH*SEQ*HD], g_vl[BH*SEQ*HD];  // V, x8
__device__ __half g_atth[TOK*CH], g_attl[TOK*CH];    // attn out, x8
__device__ __half g_wqh[CH*C3],  g_wql[CH*C3];       // w_qkv, x64
__device__ __half g_woh[CH*CH],  g_wol[CH*CH];       // w_out, x64

#define ASCALE 8.0f
#define WSCALE 64.0f
#define CINV   (1.0f/512.0f)
#define SMUL   (0.125f/64.0f)

// ---------------------------------------------------------------------------
// helpers
// ---------------------------------------------------------------------------
__device__ __forceinline__ void splitf(float x, __half& h, __half& l) {
    h = __float2half_rn(x);
    l = __float2half_rn(x - __half2float(h));
}

__device__ __forceinline__ void ldsm4(uint32_t a[4], const void* p) {
    uint32_t addr = (uint32_t)__cvta_generic_to_shared(p);
    asm volatile("ldmatrix.sync.aligned.m8n8.x4.shared.b16 {%0,%1,%2,%3}, [%4];"
                 : "=r"(a[0]), "=r"(a[1]), "=r"(a[2]), "=r"(a[3]) : "r"(addr));
}

__device__ __forceinline__ void ldsm4t(uint32_t a[4], const void* p) {
    uint32_t addr = (uint32_t)__cvta_generic_to_shared(p);
    asm volatile("ldmatrix.sync.aligned.m8n8.x4.trans.shared.b16 {%0,%1,%2,%3}, [%4];"
                 : "=r"(a[0]), "=r"(a[1]), "=r"(a[2]), "=r"(a[3]) : "r"(addr));
}

__device__ __forceinline__ void mma_f16(float c[4], const uint32_t a[4], const uint32_t b[2]) {
    asm volatile(
        "mma.sync.aligned.m16n8k16.row.col.f32.f16.f16.f32 "
        "{%0,%1,%2,%3},{%4,%5,%6,%7},{%8,%9},{%0,%1,%2,%3};"
        : "+f"(c[0]), "+f"(c[1]), "+f"(c[2]), "+f"(c[3])
        : "r"(a[0]), "r"(a[1]), "r"(a[2]), "r"(a[3]), "r"(b[0]), "r"(b[1]));
}

// ---------------------------------------------------------------------------
// 0) Weight split: dst = split(src * 64)
// ---------------------------------------------------------------------------
__global__ void wsplit_kernel(const float* __restrict__ src,
                              __half* __restrict__ dh,
                              __half* __restrict__ dl,
                              int n) {
    int i = blockIdx.x * 256 + threadIdx.x;
    if (i < n) {
        __half h, lo;
        splitf(src[i] * WSCALE, h, lo);
        dh[i] = h; dl[i] = lo;
    }
}

// ---------------------------------------------------------------------------
// 1) LayerNorm: one block per token; writes split halves (x8)
// ---------------------------------------------------------------------------
__global__ void ln_kernel(const float* __restrict__ x,
                          const float* __restrict__ gamma,
                          const float* __restrict__ beta) {
    int t = blockIdx.x;
    const float* xr = x + (size_t)t * CH;
    int i0 = threadIdx.x, i1 = i0 + 256, i2 = i0 + 512;
    float v0 = xr[i0], v1 = xr[i1], v2 = xr[i2];
    float s  = v0 + v1 + v2;
    float s2 = v0*v0 + v1*v1 + v2*v2;
    #pragma unroll
    for (int o = 16; o > 0; o >>= 1) {
        s  += __shfl_down_sync(0xffffffffu, s,  o);
        s2 += __shfl_down_sync(0xffffffffu, s2, o);
    }
    __shared__ float ws[8], ws2[8];
    __shared__ float mu_s, inv_s;
    int w = threadIdx.x >> 5, l = threadIdx.x & 31;
    if (l == 0) { ws[w] = s; ws2[w] = s2; }
    __syncthreads();
    if (threadIdx.x == 0) {
        float a = 0.f, b = 0.f;
        #pragma unroll
        for (int k = 0; k < 8; k++) { a += ws[k]; b += ws2[k]; }
        float mu  = a * (1.0f / CH);
        float var = b * (1.0f / CH) - mu * mu;
        mu_s  = mu;
        inv_s = rsqrtf(var + 1e-5f);
    }
    __syncthreads();
    float mu = mu_s, inv = inv_s;
    size_t base = (size_t)t * CH;
    __half h, lo;
    float o0 = (v0 - mu) * inv * gamma[i0] + beta[i0];
    float o1 = (v1 - mu) * inv * gamma[i1] + beta[i1];
    float o2 = (v2 - mu) * inv * gamma[i2] + beta[i2];
    splitf(o0 * ASCALE, h, lo); g_xnh[base + i0] = h; g_xnl[base + i0] = lo;
    splitf(o1 * ASCALE, h, lo); g_xnh[base + i1] = h; g_xnl[base + i1] = lo;
    splitf(o2 * ASCALE, h, lo); g_xnh[base + i2] = h; g_xnl[base + i2] = lo;
}

// ---------------------------------------------------------------------------
// GEMM config: BM=128, BN=64, BK=16, 128 threads = 4 warps (2x2),
// warp tile 64x32. Operands pre-split; epilogue rescales by 1/512.
// ---------------------------------------------------------------------------
#define GBM 128
#define GBN 64
#define GBK 16
#define HPAD 24

// 2) QKV GEMM: xn(split) @ wqkv(split) -> q/k/v written as split halves (x8)
__global__ void f16gemm_qkv() {
    __shared__ __half Ah[2][GBM][HPAD], Al[2][GBM][HPAD];
    __shared__ __half Bh[2][GBN][HPAD], Bl[2][GBN][HPAD];

    int tid = threadIdx.x;
    int w = tid >> 5, L = tid & 31;
    int wm = w >> 1, wn = w & 1;
    int m0 = blockIdx.y * GBM;
    int n0 = blockIdx.x * GBN;

    float acc[4][4][4];
    #pragma unroll
    for (int i = 0; i < 4; i++)
        #pragma unroll
        for (int j = 0; j < 4; j++)
            #pragma unroll
            for (int c = 0; c < 4; c++) acc[i][j][c] = 0.f;

    int b_n  = tid & 63;
    int b_k0 = (tid >> 6) * 8;
    const int KT = CH / GBK;

    {
        #pragma unroll
        for (int i = 0; i < 4; i++) {
            int s = tid + i * 128;
            int r = s >> 2, c = (s & 3) * 4;
            size_t off = (size_t)(m0 + r) * CH + c;
            *(uint2*)&Ah[0][r][c] = *(const uint2*)&g_xnh[off];
            *(uint2*)&Al[0][r][c] = *(const uint2*)&g_xnl[off];
        }
        #pragma unroll
        for (int j = 0; j < 8; j++) {
            size_t off = (size_t)(b_k0 + j) * C3 + n0 + b_n;
            Bh[0][b_n][b_k0 + j] = g_wqh[off];
            Bl[0][b_n][b_k0 + j] = g_wql[off];
        }
    }
    __syncthreads();

    int a_row_off = ((L >> 3) & 1) * 8 + (L & 7);
    int a_col_off = ((L >> 4) & 1) * 8;
    int b_n_off   = ((L >> 4) & 1) * 8 + (L & 7);
    int b_k_off   = ((L >> 3) & 1) * 8;

    for (int kt = 0; kt < KT; kt++) {
        int cur = kt & 1, nxt = cur ^ 1;
        uint2 pah[4], pal[4];
        __half pbh[8], pbl[8];
        bool has_next = (kt + 1 < KT);
        if (has_next) {
            int kbase = (kt + 1) * GBK;
            #pragma unroll
            for (int i = 0; i < 4; i++) {
                int s = tid + i * 128;
                int r = s >> 2, c = (s & 3) * 4;
                size_t off = (size_t)(m0 + r) * CH + kbase + c;
                pah[i] = *(const uint2*)&g_xnh[off];
                pal[i] = *(const uint2*)&g_xnl[off];
            }
            #pragma unroll
            for (int j = 0; j < 8; j++) {
                size_t off = (size_t)(kbase + b_k0 + j) * C3 + n0 + b_n;
                pbh[j] = g_wqh[off];
                pbl[j] = g_wql[off];
            }
        }
        {
            uint32_t afh[4][4], afl[4][4];
            #pragma unroll
            for (int mf = 0; mf < 4; mf++) {
                int row = wm * 64 + mf * 16 + a_row_off;
                ldsm4(afh[mf], &Ah[cur][row][a_col_off]);
                ldsm4(afl[mf], &Al[cur][row][a_col_off]);
            }
            #pragma unroll
            for (int p = 0; p < 2; p++) {
                int n = wn * 32 + p * 16 + b_n_off;
                uint32_t th[4], tl[4];
                ldsm4(th, &Bh[cur][n][b_k_off]);
                ldsm4(tl, &Bl[cur][n][b_k_off]);
                #pragma unroll
                for (int q = 0; q < 2; q++) {
                    int nf = 2 * p + q;
                    const uint32_t bh2[2] = {th[2*q], th[2*q+1]};
                    const uint32_t bl2[2] = {tl[2*q], tl[2*q+1]};
                    #pragma unroll
                    for (int mf = 0; mf < 4; mf++) {
                        mma_f16(acc[mf][nf], afh[mf], bh2);
                        mma_f16(acc[mf][nf], afh[mf], bl2);
                        mma_f16(acc[mf][nf], afl[mf], bh2);
                    }
                }
            }
        }
        if (has_next) {
            #pragma unroll
            for (int i = 0; i < 4; i++) {
                int s = tid + i * 128;
                int r = s >> 2, c = (s & 3) * 4;
                *(uint2*)&Ah[nxt][r][c] = pah[i];
                *(uint2*)&Al[nxt][r][c] = pal[i];
            }
            #pragma unroll
            for (int j = 0; j < 8; j++) {
                Bh[nxt][b_n][b_k0 + j] = pbh[j];
                Bl[nxt][b_n][b_k0 + j] = pbl[j];
            }
        }
        __syncthreads();
    }

    // epilogue: val = acc/512; store split(val*8) = split(acc/64)
    int g = L >> 2, t2 = (L & 3) * 2;
    int which = n0 / CH;
    int h = (n0 % CH) >> 6;
    __half* dsth = (which == 0) ? g_qh : ((which == 1) ? g_kh : g_vh);
    __half* dstl = (which == 0) ? g_ql : ((which == 1) ? g_kl : g_vl);
    #pragma unroll
    for (int mf = 0; mf < 4; mf++)
        #pragma unroll
        for (int nf = 0; nf < 4; nf++) {
            int d = wn * 32 + nf * 8 + t2;
            #pragma unroll
            for (int half = 0; half < 2; half++) {
                int m = m0 + wm * 64 + mf * 16 + g + half * 8;
                int b = m >> 11, n = m & (SEQ - 1);
                size_t off = ((size_t)(b * NH + h) * SEQ + n) * HD + d;
                float v0 = (float)(acc[mf][nf][half*2]  ) * CINV;
                float v1 = (float)(acc[mf][nf][half*2+1]) * CINV;
                __half h0, l0, h1, l1;
                splitf(v0 * ASCALE, h0, l0);
                splitf(v1 * ASCALE, h1, l1);
                *(__half2*)&dsth[off] = __halves2half2(h0, h1);
                *(__half2*)&dstl[off] = __halves2half2(l0, l1);
            }
        }
}

// 4) Output GEMM: att(split) @ w_out(split) + bias + residual -> fp32 out
__global__ void f16gemm_out(const float* __restrict__ bias,
                            const float* __restrict__ resid,
                            float* __restrict__ outp) {
    __shared__ __half Ah[2][GBM][HPAD], Al[2][GBM][HPAD];
    __shared__ __half Bh[2][GBN][HPAD], Bl[2][GBN][HPAD];

    int tid = threadIdx.x;
    int w = tid >> 5, L = tid & 31;
    int wm = w >> 1, wn = w & 1;
    int m0 = blockIdx.y * GBM;
    int n0 = blockIdx.x * GBN;

    float acc[4][4][4];
    #pragma unroll
    for (int i = 0; i < 4; i++)
        #pragma unroll
        for (int j = 0; j < 4; j++)
            #pragma unroll
            for (int c = 0; c < 4; c++) acc[i][j][c] = 0.f;

    int b_n  = tid & 63;
    int b_k0 = (tid >> 6) * 8;
    const int KT = CH / GBK;

    {
        #pragma unroll
        for (int i = 0; i < 4; i++) {
            int s = tid + i * 128;
            int r = s >> 2, c = (s & 3) * 4;
            size_t off = (size_t)(m0 + r) * CH + c;
            *(uint2*)&Ah[0][r][c] = *(const uint2*)&g_atth[off];
            *(uint2*)&Al[0][r][c] = *(const uint2*)&g_attl[off];
        }
        #pragma unroll
        for (int j = 0; j < 8; j++) {
            size_t off = (size_t)(b_k0 + j) * CH + n0 + b_n;
            Bh[0][b_n][b_k0 + j] = g_woh[off];
            Bl[0][b_n][b_k0 + j] = g_wol[off];
        }
    }
    __syncthreads();

    int a_row_off = ((L >> 3) & 1) * 8 + (L & 7);
    int a_col_off = ((L >> 4) & 1) * 8;
    int b_n_off   = ((L >> 4) & 1) * 8 + (L & 7);
    int b_k_off   = ((L >> 3) & 1) * 8;

    for (int kt = 0; kt < KT; kt++) {
        int cur = kt & 1, nxt = cur ^ 1;
        uint2 pah[4], pal[4];
        __half pbh[8], pbl[8];
        bool has_next = (kt + 1 < KT);
        if (has_next) {
            int kbase = (kt + 1) * GBK;
            #pragma unroll
            for (int i = 0; i < 4; i++) {
                int s = tid + i * 128;
                int r = s >> 2, c = (s & 3) * 4;
                size_t off = (size_t)(m0 + r) * CH + kbase + c;
                pah[i] = *(const uint2*)&g_atth[off];
                pal[i] = *(const uint2*)&g_attl[off];
            }
            #pragma unroll
            for (int j = 0; j < 8; j++) {
                size_t off = (size_t)(kbase + b_k0 + j) * CH + n0 + b_n;
                pbh[j] = g_woh[off];
                pbl[j] = g_wol[off];
            }
        }
        {
            uint32_t afh[4][4], afl[4][4];
            #pragma unroll
            for (int mf = 0; mf < 4; mf++) {
                int row = wm * 64 + mf * 16 + a_row_off;
                ldsm4(afh[mf], &Ah[cur][row][a_col_off]);
                ldsm4(afl[mf], &Al[cur][row][a_col_off]);
            }
            #pragma unroll
            for (int p = 0; p < 2; p++) {
                int n = wn * 32 + p * 16 + b_n_off;
                uint32_t th[4], tl[4];
                ldsm4(th, &Bh[cur][n][b_k_off]);
                ldsm4(tl, &Bl[cur][n][b_k_off]);
                #pragma unroll
                for (int q = 0; q < 2; q++) {
                    int nf = 2 * p + q;
                    const uint32_t bh2[2] = {th[2*q], th[2*q+1]};
                    const uint32_t bl2[2] = {tl[2*q], tl[2*q+1]};
                    #pragma unroll
                    for (int mf = 0; mf < 4; mf++) {
                        mma_f16(acc[mf][nf], afh[mf], bh2);
                        mma_f16(acc[mf][nf], afh[mf], bl2);
                        mma_f16(acc[mf][nf], afl[mf], bh2);
                    }
                }
            }
        }
        if (has_next) {
            #pragma unroll
            for (int i = 0; i < 4; i++) {
                int s = tid + i * 128;
                int r = s >> 2, c = (s & 3) * 4;
                *(uint2*)&Ah[nxt][r][c] = pah[i];
                *(uint2*)&Al[nxt][r][c] = pal[i];
            }
            #pragma unroll
            for (int j = 0; j < 8; j++) {
                Bh[nxt][b_n][b_k0 + j] = pbh[j];
                Bl[nxt][b_n][b_k0 + j] = pbl[j];
            }
        }
        __syncthreads();
    }

    int g = L >> 2, t2 = (L & 3) * 2;
    #pragma unroll
    for (int mf = 0; mf < 4; mf++)
        #pragma unroll
        for (int nf = 0; nf < 4; nf++) {
            int col = n0 + wn * 32 + nf * 8 + t2;
            float2 bv = *(const float2*)&bias[col];
            #pragma unroll
            for (int half = 0; half < 2; half++) {
                int m = m0 + wm * 64 + mf * 16 + g + half * 8;
                float2 rv = *(const float2*)&resid[(size_t)m * CH + col];
                float2 v = make_float2(acc[mf][nf][half*2]   * CINV + bv.x + rv.x,
                                       acc[mf][nf][half*2+1] * CINV + bv.y + rv.y);
                *(float2*)&outp[(size_t)m * CH + col] = v;
            }
        }
}

// ---------------------------------------------------------------------------
// 3) Flash attention, fp16x3 mma, pre-split Q/K/V (x8).
//    S x 0.125/64 after mma; P x64 at split; att stored split(o/(64 l)).
// ---------------------------------------------------------------------------
#define APAD 72

__global__ void f16attn() {
    __shared__ __half Kh[64][APAD], Kl[64][APAD];
    __shared__ __half Vh[64][APAD], Vl[64][APAD];

    int tid = threadIdx.x;
    int w = tid >> 5, L = tid & 31;
    int bh = blockIdx.y;
    int q0 = blockIdx.x * 64;

    size_t hb = (size_t)bh * SEQ * HD;

    int a_row_off = ((L >> 3) & 1) * 8 + (L & 7);
    int a_col_off = ((L >> 4) & 1) * 8;
    int b_n_off   = ((L >> 4) & 1) * 8 + (L & 7);
    int b_k_off   = ((L >> 3) & 1) * 8;
    int g = L >> 2, t2 = (L & 3) * 2;

    // Stage pre-split Q through Kh/Kl, build persistent fragments
    #pragma unroll
    for (int i = 0; i < 8; i++) {
        int s = tid + i * 128;
        int r = s >> 4, d4 = (s & 15) * 4;
        size_t off = hb + (size_t)(q0 + r) * HD + d4;
        *(uint2*)&Kh[r][d4] = *(const uint2*)&g_qh[off];
        *(uint2*)&Kl[r][d4] = *(const uint2*)&g_ql[off];
    }
    __syncthreads();
    uint32_t qfh[4][4], qfl[4][4];
    #pragma unroll
    for (int ks = 0; ks < 4; ks++) {
        int row = w * 16 + a_row_off;
        ldsm4(qfh[ks], &Kh[row][ks * 16 + a_col_off]);
        ldsm4(qfl[ks], &Kl[row][ks * 16 + a_col_off]);
    }

    float m0r = -1e30f, m1r = -1e30f, l0 = 0.f, l1 = 0.f;
    float oacc[8][4];
    #pragma unroll
    for (int j = 0; j < 8; j++)
        #pragma unroll
        for (int c = 0; c < 4; c++) oacc[j][c] = 0.f;

    for (int s0 = 0; s0 < SEQ; s0 += 64) {
        __syncthreads();
        // Copy pre-split K and V tiles [kv][d]
        #pragma unroll
        for (int i = 0; i < 8; i++) {
            int s = tid + i * 128;
            int kv = s >> 4, d4 = (s & 15) * 4;
            size_t off = hb + (size_t)(s0 + kv) * HD + d4;
            *(uint2*)&Kh[kv][d4] = *(const uint2*)&g_kh[off];
            *(uint2*)&Kl[kv][d4] = *(const uint2*)&g_kl[off];
            *(uint2*)&Vh[kv][d4] = *(const uint2*)&g_vh[off];
            *(uint2*)&Vl[kv][d4] = *(const uint2*)&g_vl[off];
        }
        __syncthreads();

        // S = (8Q)(8K)^T ; rescale by 0.125/64 after
        float sacc[8][4];
        #pragma unroll
        for (int j = 0; j < 8; j++)
            #pragma unroll
            for (int c = 0; c < 4; c++) sacc[j][c] = 0.f;
        #pragma unroll
        for (int ks = 0; ks < 4; ks++) {
            #pragma unroll
            for (int p = 0; p < 4; p++) {
                int n = p * 16 + b_n_off;
                uint32_t th[4], tl[4];
                ldsm4(th, &Kh[n][ks * 16 + b_k_off]);
                ldsm4(tl, &Kl[n][ks * 16 + b_k_off]);
                #pragma unroll
                for (int q = 0; q < 2; q++) {
                    int j = 2 * p + q;
                    const uint32_t bh2[2] = {th[2*q], th[2*q+1]};
                    const uint32_t bl2[2] = {tl[2*q], tl[2*q+1]};
                    mma_f16(sacc[j], qfh[ks], bh2);
                    mma_f16(sacc[j], qfh[ks], bl2);
                    mma_f16(sacc[j], qfl[ks], bh2);
                }
            }
        }
        #pragma unroll
        for (int j = 0; j < 8; j++)
            #pragma unroll
            for (int c = 0; c < 4; c++) sacc[j][c] *= SMUL;

        // Online softmax on fragments (rows g and g+8 of this warp's 16)
        float mx0 = -1e30f, mx1 = -1e30f;
        #pragma unroll
        for (int j = 0; j < 8; j++) {
            mx0 = fmaxf(mx0, fmaxf(sacc[j][0], sacc[j][1]));
            mx1 = fmaxf(mx1, fmaxf(sacc[j][2], sacc[j][3]));
        }
        #pragma unroll
        for (int o = 1; o <= 2; o <<= 1) {
            mx0 = fmaxf(mx0, __shfl_xor_sync(0xffffffffu, mx0, o));
            mx1 = fmaxf(mx1, __shfl_xor_sync(0xffffffffu, mx1, o));
        }
        float mn0 = fmaxf(m0r, mx0), mn1 = fmaxf(m1r, mx1);
        float f0 = __expf(m0r - mn0), f1 = __expf(m1r - mn1);
        m0r = mn0; m1r = mn1;
        float rs0 = 0.f, rs1 = 0.f;
        #pragma unroll
        for (int j = 0; j < 8; j++) {
            sacc[j][0] = __expf(sacc[j][0] - mn0);
            sacc[j][1] = __expf(sacc[j][1] - mn0);
            sacc[j][2] = __expf(sacc[j][2] - mn1);
            sacc[j][3] = __expf(sacc[j][3] - mn1);
            rs0 += sacc[j][0] + sacc[j][1];
            rs1 += sacc[j][2] + sacc[j][3];
        }
        #pragma unroll
        for (int o = 1; o <= 2; o <<= 1) {
            rs0 += __shfl_xor_sync(0xffffffffu, rs0, o);
            rs1 += __shfl_xor_sync(0xffffffffu, rs1, o);
        }
        l0 = l0 * f0 + rs0;
        l1 = l1 * f1 + rs1;
        #pragma unroll
        for (int j = 0; j < 8; j++) {
            oacc[j][0] *= f0; oacc[j][1] *= f0;
            oacc[j][2] *= f1; oacc[j][3] *= f1;
        }

        __syncthreads();
        // Write P (x64) split into Kh/Kl as [q][kv]
        #pragma unroll
        for (int j = 0; j < 8; j++) {
            int c0 = j * 8 + t2;
            __half h0, l0h, h1, l1h;
            splitf(sacc[j][0] * 64.0f, h0, l0h); splitf(sacc[j][1] * 64.0f, h1, l1h);
            *(__half2*)&Kh[w*16 + g][c0] = __halves2half2(h0, h1);
            *(__half2*)&Kl[w*16 + g][c0] = __halves2half2(l0h, l1h);
            splitf(sacc[j][2] * 64.0f, h0, l0h); splitf(sacc[j][3] * 64.0f, h1, l1h);
            *(__half2*)&Kh[w*16 + g + 8][c0] = __halves2half2(h0, h1);
            *(__half2*)&Kl[w*16 + g + 8][c0] = __halves2half2(l0h, l1h);
        }
        __syncthreads();

        // O += (64P)(8V)   (V via ldmatrix.trans)
        #pragma unroll
        for (int ks = 0; ks < 4; ks++) {
            uint32_t pah[4], pal[4];
            int row = w * 16 + a_row_off;
            ldsm4(pah, &Kh[row][ks * 16 + a_col_off]);
            ldsm4(pal, &Kl[row][ks * 16 + a_col_off]);
            #pragma unroll
            for (int p = 0; p < 4; p++) {
                uint32_t th[4], tl[4];
                ldsm4t(th, &Vh[ks * 16 + a_row_off][p * 16 + a_col_off]);
                ldsm4t(tl, &Vl[ks * 16 + a_row_off][p * 16 + a_col_off]);
                #pragma unroll
                for (int q = 0; q < 2; q++) {
                    int j = 2 * p + q;
                    const uint32_t bh2[2] = {th[2*q], th[2*q+1]};
                    const uint32_t bl2[2] = {tl[2*q], tl[2*q+1]};
                    mma_f16(oacc[j], pah, bh2);
                    mma_f16(oacc[j], pah, bl2);
                    mma_f16(oacc[j], pal, bh2);
                }
            }
        }
    }

    // Epilogue: o_actual = oacc/(512 l); store split(o_actual*8) = split(oacc/(64 l))
    int b = bh / NH, h = bh % NH;
    float inv0 = (1.0f / 64.0f) / l0, inv1 = (1.0f / 64.0f) / l1;
    #pragma unroll
    for (int j = 0; j < 8; j++) {
        int d = j * 8 + t2;
        int q = q0 + w * 16 + g;
        size_t off0 = ((size_t)(b * SEQ + q)) * CH + h * HD + d;
        size_t off1 = ((size_t)(b * SEQ + q + 8)) * CH + h * HD + d;
        __half h0, l0h, h1, l1h;
        splitf(oacc[j][0] * inv0, h0, l0h);
        splitf(oacc[j][1] * inv0, h1, l1h);
        *(__half2*)&g_atth[off0] = __halves2half2(h0, h1);
        *(__half2*)&g_attl[off0] = __halves2half2(l0h, l1h);
        splitf(oacc[j][2] * inv1, h0, l0h);
        splitf(oacc[j][3] * inv1, h1, l1h);
        *(__half2*)&g_atth[off1] = __halves2half2(h0, h1);
        *(__half2*)&g_attl[off1] = __halves2half2(l0h, l1h);
    }
}

// ---------------------------------------------------------------------------
extern "C" void kernel_launch(void* const* d_in, const int* in_sizes, int n_in,
                              void* d_out, int out_size) {
    const float* img   = (const float*)d_in[0];
    const float* gamma = (const float*)d_in[1];
    const float* beta  = (const float*)d_in[2];
    const float* w_qkv = (const float*)d_in[3];
    const float* w_out = (const float*)d_in[4];
    const float* b_out = (const float*)d_in[5];
    float* out = (float*)d_out;

    __half *wqh, *wql, *woh, *wol;
    cudaGetSymbolAddress((void**)&wqh, g_wqh);
    cudaGetSymbolAddress((void**)&wql, g_wql);
    cudaGetSymbolAddress((void**)&woh, g_woh);
    cudaGetSymbolAddress((void**)&wol, g_wol);

    wsplit_kernel<<<(CH * C3 + 255) / 256, 256>>>(w_qkv, wqh, wql, CH * C3);
    wsplit_kernel<<<(CH * CH + 255) / 256, 256>>>(w_out, woh, wol, CH * CH);
    ln_kernel<<<TOK, 256>>>(img, gamma, beta);
    f16gemm_qkv<<<dim3(C3 / GBN, TOK / GBM), 128>>>();
    f16attn<<<dim3(SEQ / 64, BH), 128>>>();
    f16gemm_out<<<dim3(CH / GBN, TOK / GBM), 128>>>(b_out, img, out);
}